// round 17
// baseline (speedup 1.0000x reference)
#include <cuda_runtime.h>
#include <cuda_bf16.h>
#include <cstdint>

// Problem constants (H=W=256, SMALL=8, LARGE=16, B=2)
#define HW      65536
#define NB      2
#define WNUM    1024
#define S2      64
#define L2      256
#define NTILE   (WNUM*NB)     // 2048
#define NBLK    1024          // single wave at occ 7 (148*7 = 1036)
#define NCORRB  256
#define K1      18            // static bulk iters, corr blocks
#define K2      31            // static bulk iters, plain blocks
#define TCH     272           // stolen tail: 272 block-chunks x 16 iters
// static: 256*18*256 + 768*31*256 = 1179648 + 6094848 = 7274496
// tail:   272*16*256 = 1114112 ;  7274496 + 1114112 = 8388608 = all of P
#define CORR_REGION 1179648
#define STATIC_END  7274496

__device__ int    g_partner[NB * HW];     // 512 KB (L2-resident)
__device__ float2 g_corr[NTILE];          // {nll_sum/c_num, absd_corr}
__device__ float  g_bulk[NBLK];           // static-part block partials
__device__ float  g_tailp[TCH * 8];       // tail per-(chunk,warp) partials
__device__ int    g_sync1;                // scatter barrier (rearmed)
__device__ int    g_tail;                 // tail chunk claim counter (rearmed)
__device__ int    g_ticket;               // completion ticket (rearmed)

__device__ __forceinline__ float warp_sum(float v) {
    #pragma unroll
    for (int o = 16; o > 0; o >>= 1) v += __shfl_down_sync(0xFFFFFFFFu, v, o);
    return v;
}

// ---------------------------------------------------------------------------
// Static body (R6 structure) + block-stolen tail with per-warp deterministic
// partials. Hot loops stay sync/atomic-free; stealing only at the end.
// ---------------------------------------------------------------------------
__global__ __launch_bounds__(256, 7)
void k_all(const float4* __restrict__ P4,
           const float*  __restrict__ Pf,
           const int*    __restrict__ index_r,
           const int*    __restrict__ lw_abs,
           float*        __restrict__ out) {
    const int bid  = blockIdx.x;
    const int tid  = threadIdx.x;
    const int lane = tid & 31;
    const int wrp  = tid >> 5;

    float a0 = 0.f, a1 = 0.f;

    if (bid < NCORRB) {
        // ---- scatter slice: 512 entries ----
        #pragma unroll
        for (int r = 0; r < 2; r++) {
            int e    = bid * 512 + r * 256 + tid;      // covers NB*HW exactly
            int b    = e >> 16;
            int j    = e & (HW - 1);
            int idx0 = index_r[(b * 2 + 0) * HW + j];
            int idx1 = index_r[(b * 2 + 1) * HW + j];
            g_partner[b * HW + idx1] = idx0;
        }
        __threadfence();
        __syncthreads();
        if (tid == 0) atomicAdd(&g_sync1, 1);   // arrive early, wait later

        // ---- static bulk share (contiguous region) ----
        const int base = bid * (K1 * 256) + tid;
        #pragma unroll 4
        for (int k = 0; k < K1; k++) {
            float4 p = __ldcs(P4 + base + k * 256);
            a0 += p.x + p.y;
            a1 += p.z + p.w;
        }

        // ---- barrier wait (long drained) ----
        if (tid == 0) {
            while (*((volatile int*)&g_sync1) < NCORRB) { }
        }
        __syncthreads();
        __threadfence();

        // ---- per-warp tile corrections (tile = bid*8 + warp) ----
        const int tile = bid * 8 + wrp;
        const int w    = tile >> 1;
        const int b    = tile & 1;
        const int r0   = (w >> 5) << 3;
        const int c0   = (w & 31) << 3;
        const float* Pt = Pf + (size_t)tile * (S2 * L2);

        float absd = 0.f, nll = 0.f;
        int   cnt  = 0;
        #pragma unroll
        for (int k = 0; k < 8; k++) {
            int l  = lane + 32 * k;
            int lw = __ldg(lw_abs + w * L2 + l);
            int v  = g_partner[b * HW + lw];             // plw
            int i  = (v >> 8) - r0;
            int j  = (v & 255) - c0;
            if ((unsigned)i < 8u && (unsigned)j < 8u && !(v == 0 && lw == 0)) {
                float p = __ldg(Pt + (i * 8 + j) * L2 + l);
                absd += 1.f - 2.f * p;                   // |p-1| - p
                nll  -= __logf(fminf(fmaxf(p, 1e-6f), 1.f - 1e-6f));
                cnt++;
            }
        }
        float cntf = (float)cnt;
        absd = warp_sum(absd);
        nll  = warp_sum(nll);
        cntf = warp_sum(cntf);
        if (lane == 0) g_corr[tile] = make_float2(nll / cntf, absd);
        if (lane == 0) a1 += absd;   // fold absd corr into bulk partial once
    } else {
        // ---- plain block: static bulk only, zero preamble ----
        const int base = CORR_REGION + (bid - NCORRB) * (K2 * 256) + tid;
        #pragma unroll 4
        for (int k = 0; k < K2; k++) {
            float4 p = __ldcs(P4 + base + k * 256);
            a0 += p.x + p.y;
            a1 += p.z + p.w;
        }
    }

    // ---- static block partial (value independent of tail stealing) ----
    {
        float acc = warp_sum(a0 + a1);
        __shared__ float red[8];
        if (lane == 0) red[wrp] = acc;
        __syncthreads();
        if (wrp == 0) {
            float a = (lane < 8) ? red[lane] : 0.f;
            #pragma unroll
            for (int o = 4; o > 0; o >>= 1) a += __shfl_down_sync(0xFFFFFFFFu, a, o);
            if (lane == 0) g_bulk[bid] = a;
        }
    }

    // ---- stolen tail: block-level claims, per-warp deterministic partials ----
    {
        __shared__ int s_c[2];
        int slot = 0;
        for (;;) {
            if (tid == 0) s_c[slot] = atomicAdd(&g_tail, 1);
            __syncthreads();
            const int c = s_c[slot];
            slot ^= 1;
            __syncthreads();              // allow next claim to reuse other slot
            if (c >= TCH) break;

            const int base = STATIC_END + c * 4096 + tid;
            float t0 = 0.f, t1 = 0.f;
            #pragma unroll 4
            for (int k = 0; k < 16; k++) {
                float4 p = __ldcs(P4 + base + k * 256);
                t0 += p.x + p.y;
                t1 += p.z + p.w;
            }
            float ts = warp_sum(t0 + t1);          // function of (c, wrp) only
            if (lane == 0) g_tailp[c * 8 + wrp] = ts;
        }
    }

    // ---- completion ticket ----
    __shared__ bool s_last;
    __syncthreads();
    if (tid == 0) {
        __threadfence();
        int t = atomicAdd(&g_ticket, 1);
        s_last = (t == NBLK - 1);
    }
    __syncthreads();

    // ---- final fixed-order combine (deterministic) ----
    if (s_last) {
        float sumP = 0.f, sumR = 0.f;
        for (int i = tid; i < NBLK; i += 256) sumP += g_bulk[i];
        for (int i = tid; i < TCH * 8; i += 256) sumP += g_tailp[i];
        for (int i = tid; i < NTILE; i += 256) sumR += g_corr[i].x;
        sumP = warp_sum(sumP);
        sumR = warp_sum(sumR);
        __shared__ float sp[8], sr[8];
        if (lane == 0) { sp[wrp] = sumP; sr[wrp] = sumR; }
        __syncthreads();
        if (wrp == 0) {
            float p = (lane < 8) ? sp[lane] : 0.f;
            float r = (lane < 8) ? sr[lane] : 0.f;
            #pragma unroll
            for (int o = 4; o > 0; o >>= 1) {
                p += __shfl_down_sync(0xFFFFFFFFu, p, o);
                r += __shfl_down_sync(0xFFFFFFFFu, r, o);
            }
            if (lane == 0) {
                out[0] = r / (float)NTILE;                        // l_cm
                out[1] = p / (float)((size_t)NTILE * S2 * L2);    // l_c
                g_ticket = 0;                                     // rearm
                g_sync1  = 0;
                g_tail   = 0;
            }
        }
    }
}

// ---------------------------------------------------------------------------
// Launch.  Inputs: [0] P f32, [1] index_r i32, [2] sw_abs i32, [3] lw_abs i32.
// ---------------------------------------------------------------------------
extern "C" void kernel_launch(void* const* d_in, const int* in_sizes, int n_in,
                              void* d_out, int out_size) {
    const float4* P4     = (const float4*)d_in[0];
    const float*  Pf     = (const float*)d_in[0];
    const int*    idxr   = (const int*)d_in[1];
    const int*    lw_abs = (const int*)d_in[3];
    float*        out    = (float*)d_out;

    k_all<<<NBLK, 256>>>(P4, Pf, idxr, lw_abs, out);
}